// round 7
// baseline (speedup 1.0000x reference)
#include <cuda_runtime.h>
#include <cstddef>

#define THREADS 128
#define GPB 16            // graphs per block (8 lane-groups x 2 graphs/thread)

// Output layout: concat of recon[B,4,13,13], mu[B,13,16], logvar[B,13,16] (fp32)
#define R_MU 22151168ull
#define R_LV 28966912ull

typedef unsigned long long u64;

__device__ __forceinline__ void ffma2(u64 &d, u64 a, u64 b) {
    asm("fma.rn.f32x2 %0, %1, %2, %0;" : "+l"(d) : "l"(a), "l"(b));
}
__device__ __forceinline__ u64 pack2(float lo, float hi) {
    u64 r; asm("mov.b64 %0, {%1, %2};" : "=l"(r) : "f"(lo), "f"(hi)); return r;
}
__device__ __forceinline__ float2 unpack2(u64 v) {
    float2 r; asm("mov.b64 {%0, %1}, %2;" : "=f"(r.x), "=f"(r.y) : "l"(v)); return r;
}
__device__ __forceinline__ float leaky(float v) { return v >= 0.f ? v : 0.01f * v; }
__device__ __forceinline__ u64 plo(float4 w) { return pack2(w.x, w.y); }
__device__ __forceinline__ u64 phi(float4 w) { return pack2(w.z, w.w); }

// 16-wide dot, 2 accumulator chains
__device__ __forceinline__ float dot16s(const u64* pw, const u64* a2) {
    u64 accA = 0ull, accB = 0ull;
#pragma unroll
    for (int q = 0; q < 4; q++) ffma2(accA, a2[q],     pw[q]);
#pragma unroll
    for (int q = 0; q < 4; q++) ffma2(accB, a2[q + 4], pw[q + 4]);
    float2 fa = unpack2(accA), fb = unpack2(accB);
    return (fa.x + fb.x) + (fa.y + fb.y);
}

// All warp-uniform parameters live in constant memory (read via constant port,
// not L1tex). Filled per-launch by graph-capturable D2D memcpys.
struct __align__(16) CParams {
    float4 w0[256];      // mlp_w0  [l][e][4]
    float4 w1[256];      // mlp_w1
    float4 dec[256];     // dec_w   [k][d][4]
    float4 fc1[64];
    float4 fc2[64];
    float4 winit[52];    // init_weight rows
    float  b0[64], b1[64], decb[64];
    float  fc1b[16], fc2b[16];
    float  eps[4];
};
__constant__ CParams cp;

struct __align__(16) Smem {
    float  adj[GPB * 676];     // per-g: [i*169 + n*13 + m]; reused as recon staging
    float4 xsv[GPB * 65];      // per-g node rows, pitch 5 float4
};

__global__ __launch_bounds__(THREADS, 3) void vae_fused(
    const float* __restrict__ adj,
    const float* __restrict__ bn_in_gamma,  const float* __restrict__ bn_in_beta,
    const float* __restrict__ bn_in_mean,   const float* __restrict__ bn_in_var,
    const float* __restrict__ bn_out_gamma, const float* __restrict__ bn_out_beta,
    const float* __restrict__ bn_out_mean,  const float* __restrict__ bn_out_var,
    float* __restrict__ out)
{
    extern __shared__ Smem sm[];
    Smem& s = sm[0];
    const int tid = threadIdx.x;

    {   // adj for this block's 16 graphs (contiguous float4)
        const float4* src = (const float4*)(adj + (size_t)blockIdx.x * (GPB * 676));
        float4* dst = (float4*)s.adj;
        for (int i = tid; i < GPB * 169; i += THREADS) dst[i] = src[i];
    }
    __syncthreads();

    const int grp = tid >> 4;          // 0..7
    const int n   = tid & 15;          // node; lanes 13..15 idle for compute
    const int g0  = grp * 2;
    const size_t b0g = (size_t)blockIdx.x * GPB + g0;
    const float* ad[2] = { s.adj + g0 * 676, s.adj + (g0 + 1) * 676 };
    float4*      xp[2] = { s.xsv + g0 * 65,  s.xsv + (g0 + 1) * 65 };
    const bool act = (n < 13);
    const int nn = act ? n : 0;

    float x[2][16];

    // ---- init: x[n,:] = sum_m (sum_i adj[i,n,m]) * W[m,:]
    if (act) {
        float as[2][13];
#pragma unroll
        for (int g = 0; g < 2; g++)
#pragma unroll
            for (int m = 0; m < 13; m++)
                as[g][m] = ad[g][n*13+m] + ad[g][169+n*13+m] + ad[g][338+n*13+m] + ad[g][507+n*13+m];
        u64 x2[2][8];
#pragma unroll
        for (int g = 0; g < 2; g++)
#pragma unroll
            for (int q = 0; q < 8; q++) x2[g][q] = 0ull;
#pragma unroll
        for (int m = 0; m < 13; m++) {
            float4 w0_ = cp.winit[m*4],   w1_ = cp.winit[m*4+1];
            float4 w2_ = cp.winit[m*4+2], w3_ = cp.winit[m*4+3];
            u64 pw[8] = { plo(w0_), phi(w0_), plo(w1_), phi(w1_),
                          plo(w2_), phi(w2_), plo(w3_), phi(w3_) };
#pragma unroll
            for (int g = 0; g < 2; g++) {
                u64 a = pack2(as[g][m], as[g][m]);
#pragma unroll
                for (int q = 0; q < 8; q++) ffma2(x2[g][q], a, pw[q]);
            }
        }
#pragma unroll
        for (int g = 0; g < 2; g++) {
#pragma unroll
            for (int q = 0; q < 8; q++) { float2 f = unpack2(x2[g][q]); x[g][2*q] = f.x; x[g][2*q+1] = f.y; }
#pragma unroll
            for (int q = 0; q < 4; q++)
                xp[g][n*5 + q] = make_float4(x[g][4*q], x[g][4*q+1], x[g][4*q+2], x[g][4*q+3]);
        }
    }
    __syncwarp();

    // ---- 4 GIN layers ----
#pragma unroll 1
    for (int l = 0; l < 4; l++) {
        const int pi = l * 13 + nn;
        const float si = bn_in_gamma[pi]  * rsqrtf(bn_in_var[pi]  + 1e-5f);
        const float ti = bn_in_beta[pi]   - bn_in_mean[pi]  * si;
        const float so = bn_out_gamma[pi] * rsqrtf(bn_out_var[pi] + 1e-5f);
        const float to = bn_out_beta[pi]  - bn_out_mean[pi] * so;
        if (act) {
            const float ep = 1.f + cp.eps[l];
            u64 agg2[2][8];
#pragma unroll
            for (int g = 0; g < 2; g++)
#pragma unroll
                for (int q = 0; q < 8; q++) agg2[g][q] = pack2(ep * x[g][2*q], ep * x[g][2*q+1]);
#pragma unroll
            for (int i = 0; i < 4; i++) {
#pragma unroll
                for (int m = 0; m < 13; m++) {
#pragma unroll
                    for (int g = 0; g < 2; g++) {
                        float av = ad[g][i*169 + n*13 + m];
                        u64 a = pack2(av, av);
                        float4 xr = xp[g][m*5 + i];
                        ffma2(agg2[g][2*i],     a, plo(xr));
                        ffma2(agg2[g][2*i + 1], a, phi(xr));
                    }
                }
            }
            float h1[2][16];
#pragma unroll
            for (int e = 0; e < 16; e++) {
                float4 wa = cp.w0[l*64 + e*4],   wb = cp.w0[l*64 + e*4 + 1];
                float4 wc = cp.w0[l*64 + e*4+2], wd = cp.w0[l*64 + e*4 + 3];
                u64 pw[8] = { plo(wa), phi(wa), plo(wb), phi(wb),
                              plo(wc), phi(wc), plo(wd), phi(wd) };
                float bb = cp.b0[l*16 + e];
#pragma unroll
                for (int g = 0; g < 2; g++)
                    h1[g][e] = leaky(si * (dot16s(pw, agg2[g]) + bb) + ti);
            }
            u64 h2[2][8];
#pragma unroll
            for (int g = 0; g < 2; g++)
#pragma unroll
                for (int q = 0; q < 8; q++) h2[g][q] = pack2(h1[g][2*q], h1[g][2*q+1]);
#pragma unroll
            for (int e = 0; e < 16; e++) {
                float4 wa = cp.w1[l*64 + e*4],   wb = cp.w1[l*64 + e*4 + 1];
                float4 wc = cp.w1[l*64 + e*4+2], wd = cp.w1[l*64 + e*4 + 3];
                u64 pw[8] = { plo(wa), phi(wa), plo(wb), phi(wb),
                              plo(wc), phi(wc), plo(wd), phi(wd) };
                float bb = cp.b1[l*16 + e];
#pragma unroll
                for (int g = 0; g < 2; g++)
                    x[g][e] = leaky(so * (dot16s(pw, h2[g]) + bb) + to);
            }
        }
        __syncwarp();
        if (act) {
#pragma unroll
            for (int g = 0; g < 2; g++)
#pragma unroll
                for (int q = 0; q < 4; q++)
                    xp[g][n*5 + q] = make_float4(x[g][4*q], x[g][4*q+1], x[g][4*q+2], x[g][4*q+3]);
        }
        __syncwarp();
    }

    // ---- heads: mu / logvar ----
    float mu[2][16];
    {
        float lv[2][16];
        if (act) {
            u64 x2[2][8];
#pragma unroll
            for (int g = 0; g < 2; g++)
#pragma unroll
                for (int q = 0; q < 8; q++) x2[g][q] = pack2(x[g][2*q], x[g][2*q+1]);
#pragma unroll
            for (int e = 0; e < 16; e++) {
                float4 a1 = cp.fc1[e*4], b1_ = cp.fc1[e*4+1], c1 = cp.fc1[e*4+2], d1 = cp.fc1[e*4+3];
                float4 a2 = cp.fc2[e*4], b2_ = cp.fc2[e*4+1], c2 = cp.fc2[e*4+2], d2 = cp.fc2[e*4+3];
                u64 p1[8] = { plo(a1), phi(a1), plo(b1_), phi(b1_), plo(c1), phi(c1), plo(d1), phi(d1) };
                u64 p2[8] = { plo(a2), phi(a2), plo(b2_), phi(b2_), plo(c2), phi(c2), plo(d2), phi(d2) };
#pragma unroll
                for (int g = 0; g < 2; g++) {
                    mu[g][e] = dot16s(p1, x2[g]) + cp.fc1b[e];
                    lv[g][e] = dot16s(p2, x2[g]) + cp.fc2b[e];
                }
            }
        }
        __syncwarp();
        if (act) {
#pragma unroll
            for (int g = 0; g < 2; g++)
#pragma unroll
                for (int q = 0; q < 4; q++)
                    xp[g][n*5 + q] = make_float4(lv[g][4*q], lv[g][4*q+1], lv[g][4*q+2], lv[g][4*q+3]);
        }
        __syncwarp();
#pragma unroll
        for (int g = 0; g < 2; g++) {
            float4* o4 = (float4*)(out + R_LV + (b0g + g) * 208);
#pragma unroll
            for (int it = 0; it < 4; it++) {
                int idx = it * 16 + n;
                if (idx < 52) o4[idx] = xp[g][(idx >> 2) * 5 + (idx & 3)];
            }
        }
        __syncwarp();
        if (act) {
#pragma unroll
            for (int g = 0; g < 2; g++)
#pragma unroll
                for (int q = 0; q < 4; q++)
                    xp[g][n*5 + q] = make_float4(mu[g][4*q], mu[g][4*q+1], mu[g][4*q+2], mu[g][4*q+3]);
        }
        __syncwarp();
#pragma unroll
        for (int g = 0; g < 2; g++) {
            float4* o4 = (float4*)(out + R_MU + (b0g + g) * 208);
#pragma unroll
            for (int it = 0; it < 4; it++) {
                int idx = it * 16 + n;
                if (idx < 52) o4[idx] = xp[g][(idx >> 2) * 5 + (idx & 3)];
            }
        }
    }

    // ---- decoder: recon staged into the (dead) adj slice, then coalesced out ----
    u64 mu2[2][8];
    if (act) {
#pragma unroll
        for (int g = 0; g < 2; g++)
#pragma unroll
            for (int q = 0; q < 8; q++) mu2[g][q] = pack2(mu[g][2*q], mu[g][2*q+1]);
    }
    float* rec[2] = { (float*)ad[0], (float*)ad[1] };   // 676 floats each, 16B-aligned

#pragma unroll 1
    for (int k = 0; k < 4; k++) {
        __syncwarp();
        float t[2][16];
        if (act) {
#pragma unroll
            for (int d = 0; d < 16; d++) {
                float4 wa = cp.dec[k*64 + d*4],   wb = cp.dec[k*64 + d*4 + 1];
                float4 wc = cp.dec[k*64 + d*4+2], wd = cp.dec[k*64 + d*4 + 3];
                u64 pw[8] = { plo(wa), phi(wa), plo(wb), phi(wb),
                              plo(wc), phi(wc), plo(wd), phi(wd) };
                float bb = cp.decb[k*16 + d];
#pragma unroll
                for (int g = 0; g < 2; g++)
                    t[g][d] = dot16s(pw, mu2[g]) + bb;
            }
#pragma unroll
            for (int g = 0; g < 2; g++)
#pragma unroll
                for (int q = 0; q < 4; q++)
                    xp[g][n*5 + q] = make_float4(t[g][4*q], t[g][4*q+1], t[g][4*q+2], t[g][4*q+3]);
        }
        __syncwarp();
        if (act) {
#pragma unroll
            for (int g = 0; g < 2; g++) {
                u64 t2[8];
#pragma unroll
                for (int q = 0; q < 8; q++) t2[q] = pack2(t[g][2*q], t[g][2*q+1]);
                float* rr = rec[g] + k * 169 + n * 13;
#pragma unroll
                for (int m = 0; m < 13; m++) {
                    u64 accA = 0ull, accB = 0ull;
#pragma unroll
                    for (int q = 0; q < 2; q++) {
                        float4 xr = xp[g][m*5 + q];
                        ffma2(accA, t2[2*q],     plo(xr));
                        ffma2(accA, t2[2*q + 1], phi(xr));
                    }
#pragma unroll
                    for (int q = 2; q < 4; q++) {
                        float4 xr = xp[g][m*5 + q];
                        ffma2(accB, t2[2*q],     plo(xr));
                        ffma2(accB, t2[2*q + 1], phi(xr));
                    }
                    float2 fa = unpack2(accA), fb = unpack2(accB);
                    float sv = (fa.x + fb.x) + (fa.y + fb.y);
                    rr[m] = sv > 0.f ? sv : 0.f;
                }
            }
        }
    }
    __syncwarp();
    // coalesced recon writeout: 676 floats = 169 float4 per graph
#pragma unroll
    for (int g = 0; g < 2; g++) {
        const float4* r4 = (const float4*)rec[g];
        float4* o4 = (float4*)(out + (b0g + g) * 676);
#pragma unroll
        for (int it = 0; it < 11; it++) {
            int idx = it * 16 + n;
            if (idx < 169) o4[idx] = r4[idx];
        }
    }
}

extern "C" void kernel_launch(void* const* d_in, const int* in_sizes, int n_in,
                              void* d_out, int out_size) {
    (void)in_sizes; (void)n_in; (void)out_size;

    // Fill constant memory from device inputs (D2D, graph-capturable memcpy nodes)
    cudaMemcpyToSymbolAsync(cp, d_in[3],  4096, offsetof(CParams, w0),    cudaMemcpyDeviceToDevice);
    cudaMemcpyToSymbolAsync(cp, d_in[5],  4096, offsetof(CParams, w1),    cudaMemcpyDeviceToDevice);
    cudaMemcpyToSymbolAsync(cp, d_in[19], 4096, offsetof(CParams, dec),   cudaMemcpyDeviceToDevice);
    cudaMemcpyToSymbolAsync(cp, d_in[15], 1024, offsetof(CParams, fc1),   cudaMemcpyDeviceToDevice);
    cudaMemcpyToSymbolAsync(cp, d_in[17], 1024, offsetof(CParams, fc2),   cudaMemcpyDeviceToDevice);
    cudaMemcpyToSymbolAsync(cp, d_in[1],  832,  offsetof(CParams, winit), cudaMemcpyDeviceToDevice);
    cudaMemcpyToSymbolAsync(cp, d_in[4],  256,  offsetof(CParams, b0),    cudaMemcpyDeviceToDevice);
    cudaMemcpyToSymbolAsync(cp, d_in[6],  256,  offsetof(CParams, b1),    cudaMemcpyDeviceToDevice);
    cudaMemcpyToSymbolAsync(cp, d_in[20], 256,  offsetof(CParams, decb),  cudaMemcpyDeviceToDevice);
    cudaMemcpyToSymbolAsync(cp, d_in[16], 64,   offsetof(CParams, fc1b),  cudaMemcpyDeviceToDevice);
    cudaMemcpyToSymbolAsync(cp, d_in[18], 64,   offsetof(CParams, fc2b),  cudaMemcpyDeviceToDevice);
    cudaMemcpyToSymbolAsync(cp, d_in[2],  16,   offsetof(CParams, eps),   cudaMemcpyDeviceToDevice);

    cudaFuncSetAttribute(vae_fused, cudaFuncAttributeMaxDynamicSharedMemorySize,
                         (int)sizeof(Smem));
    vae_fused<<<32768 / GPB, THREADS, sizeof(Smem)>>>(
        (const float*)d_in[0],
        (const float*)d_in[7],  (const float*)d_in[8],
        (const float*)d_in[9],  (const float*)d_in[10],
        (const float*)d_in[11], (const float*)d_in[12],
        (const float*)d_in[13], (const float*)d_in[14],
        (float*)d_out);
}

// round 8
// speedup vs baseline: 1.1381x; 1.1381x over previous
#include <cuda_runtime.h>
#include <cstddef>

#define THREADS 128
#define GPB 8             // graphs per block, one per 16-lane group

// Output layout: concat of recon[B,4,13,13], mu[B,13,16], logvar[B,13,16] (fp32)
#define R_MU 22151168ull
#define R_LV 28966912ull

typedef unsigned long long u64;

__device__ __forceinline__ void ffma2(u64 &d, u64 a, u64 b) {
    asm("fma.rn.f32x2 %0, %1, %2, %0;" : "+l"(d) : "l"(a), "l"(b));
}
__device__ __forceinline__ u64 pack2(float lo, float hi) {
    u64 r; asm("mov.b64 %0, {%1, %2};" : "=l"(r) : "f"(lo), "f"(hi)); return r;
}
__device__ __forceinline__ float2 unpack2(u64 v) {
    float2 r; asm("mov.b64 {%0, %1}, %2;" : "=f"(r.x), "=f"(r.y) : "l"(v)); return r;
}
__device__ __forceinline__ float leaky(float v) { return v >= 0.f ? v : 0.01f * v; }
__device__ __forceinline__ u64 plo(float4 w) { return pack2(w.x, w.y); }
__device__ __forceinline__ u64 phi(float4 w) { return pack2(w.z, w.w); }

// 16-wide dot, 2 accumulator chains
__device__ __forceinline__ float dot16s(const u64* pw, const u64* a2) {
    u64 accA = 0ull, accB = 0ull;
#pragma unroll
    for (int q = 0; q < 4; q++) ffma2(accA, a2[q],     pw[q]);
#pragma unroll
    for (int q = 0; q < 4; q++) ffma2(accB, a2[q + 4], pw[q + 4]);
    float2 fa = unpack2(accA), fb = unpack2(accB);
    return (fa.x + fb.x) + (fa.y + fb.y);
}

// Hot mainloop weights on the constant port (3 memcpy nodes per launch)
struct __align__(16) CParams {
    float4 w0[256];      // mlp_w0  [l][e][4]
    float4 w1[256];      // mlp_w1
    float4 dec[256];     // dec_w   [k][d][4]
};
__constant__ CParams cp;

struct __align__(16) Smem {
    float  adj[GPB * 676];     // per-g: [i*169 + n*13 + m]; reused as recon staging
    float4 xsv[GPB * 65];      // per-g node rows, pitch 5 float4
};

__global__ __launch_bounds__(THREADS, 5) void vae_fused(
    const float* __restrict__ adj,
    const float* __restrict__ init_weight,
    const float* __restrict__ eps_param,
    const float* __restrict__ mlp_b0, const float* __restrict__ mlp_b1,
    const float* __restrict__ bn_in_gamma,  const float* __restrict__ bn_in_beta,
    const float* __restrict__ bn_in_mean,   const float* __restrict__ bn_in_var,
    const float* __restrict__ bn_out_gamma, const float* __restrict__ bn_out_beta,
    const float* __restrict__ bn_out_mean,  const float* __restrict__ bn_out_var,
    const float* __restrict__ fc1_w, const float* __restrict__ fc1_b,
    const float* __restrict__ fc2_w, const float* __restrict__ fc2_b,
    const float* __restrict__ dec_b,
    float* __restrict__ out)
{
    extern __shared__ Smem sm[];
    Smem& s = sm[0];
    const int tid = threadIdx.x;

    {   // adj for this block's graphs (contiguous float4)
        const float4* src = (const float4*)(adj + (size_t)blockIdx.x * (GPB * 676));
        float4* dst = (float4*)s.adj;
        for (int i = tid; i < GPB * 169; i += THREADS) dst[i] = src[i];
    }
    __syncthreads();

    const int grp = tid >> 4;          // 0..7
    const int n   = tid & 15;          // node; lanes 13..15 idle for compute
    const size_t b = (size_t)blockIdx.x * GPB + grp;
    const float* ad = s.adj + grp * 676;
    float4*      xp = s.xsv + grp * 65;
    const bool act = (n < 13);
    const int nn = act ? n : 0;

    float x[16];

    // ---- init: x[n,:] = sum_m (sum_i adj[i,n,m]) * W[m,:]
    if (act) {
        float as[13];
#pragma unroll
        for (int m = 0; m < 13; m++)
            as[m] = ad[n*13+m] + ad[169+n*13+m] + ad[338+n*13+m] + ad[507+n*13+m];
        u64 x2[8];
#pragma unroll
        for (int q = 0; q < 8; q++) x2[q] = 0ull;
#pragma unroll
        for (int m = 0; m < 13; m++) {
            const float4* wr = (const float4*)init_weight + m * 4;
            float4 w0_ = __ldg(wr), w1_ = __ldg(wr+1), w2_ = __ldg(wr+2), w3_ = __ldg(wr+3);
            u64 a = pack2(as[m], as[m]);
            ffma2(x2[0], a, plo(w0_)); ffma2(x2[1], a, phi(w0_));
            ffma2(x2[2], a, plo(w1_)); ffma2(x2[3], a, phi(w1_));
            ffma2(x2[4], a, plo(w2_)); ffma2(x2[5], a, phi(w2_));
            ffma2(x2[6], a, plo(w3_)); ffma2(x2[7], a, phi(w3_));
        }
#pragma unroll
        for (int q = 0; q < 8; q++) { float2 f = unpack2(x2[q]); x[2*q] = f.x; x[2*q+1] = f.y; }
#pragma unroll
        for (int q = 0; q < 4; q++)
            xp[n*5 + q] = make_float4(x[4*q], x[4*q+1], x[4*q+2], x[4*q+3]);
    }
    __syncwarp();

    // ---- 4 GIN layers ----
#pragma unroll 1
    for (int l = 0; l < 4; l++) {
        const int pi = l * 13 + nn;
        const float si = __ldg(bn_in_gamma + pi)  * rsqrtf(__ldg(bn_in_var + pi)  + 1e-5f);
        const float ti = __ldg(bn_in_beta + pi)   - __ldg(bn_in_mean + pi)  * si;
        const float so = __ldg(bn_out_gamma + pi) * rsqrtf(__ldg(bn_out_var + pi) + 1e-5f);
        const float to = __ldg(bn_out_beta + pi)  - __ldg(bn_out_mean + pi) * so;
        if (act) {
            const float ep = 1.f + __ldg(eps_param + l);
            u64 agg2[8];
#pragma unroll
            for (int q = 0; q < 8; q++) agg2[q] = pack2(ep * x[2*q], ep * x[2*q+1]);
#pragma unroll
            for (int i = 0; i < 4; i++) {
                const float* arow = ad + i*169 + n*13;
#pragma unroll
                for (int m = 0; m < 13; m++) {
                    float av = arow[m];
                    u64 a = pack2(av, av);
                    float4 xr = xp[m*5 + i];
                    ffma2(agg2[2*i],     a, plo(xr));
                    ffma2(agg2[2*i + 1], a, phi(xr));
                }
            }
            float h1[16];
#pragma unroll
            for (int e = 0; e < 16; e++) {
                float4 wa = cp.w0[l*64 + e*4],     wb = cp.w0[l*64 + e*4 + 1];
                float4 wc = cp.w0[l*64 + e*4 + 2], wd = cp.w0[l*64 + e*4 + 3];
                u64 pw[8] = { plo(wa), phi(wa), plo(wb), phi(wb),
                              plo(wc), phi(wc), plo(wd), phi(wd) };
                float bb = __ldg(mlp_b0 + l*16 + e);
                h1[e] = leaky(si * (dot16s(pw, agg2) + bb) + ti);
            }
            u64 h2[8];
#pragma unroll
            for (int q = 0; q < 8; q++) h2[q] = pack2(h1[2*q], h1[2*q+1]);
#pragma unroll
            for (int e = 0; e < 16; e++) {
                float4 wa = cp.w1[l*64 + e*4],     wb = cp.w1[l*64 + e*4 + 1];
                float4 wc = cp.w1[l*64 + e*4 + 2], wd = cp.w1[l*64 + e*4 + 3];
                u64 pw[8] = { plo(wa), phi(wa), plo(wb), phi(wb),
                              plo(wc), phi(wc), plo(wd), phi(wd) };
                float bb = __ldg(mlp_b1 + l*16 + e);
                x[e] = leaky(so * (dot16s(pw, h2) + bb) + to);
            }
        }
        __syncwarp();
        if (act) {
#pragma unroll
            for (int q = 0; q < 4; q++)
                xp[n*5 + q] = make_float4(x[4*q], x[4*q+1], x[4*q+2], x[4*q+3]);
        }
        __syncwarp();
    }

    // ---- heads: mu / logvar ----
    float mu[16];
    {
        float lv[16];
        if (act) {
            u64 x2[8];
#pragma unroll
            for (int q = 0; q < 8; q++) x2[q] = pack2(x[2*q], x[2*q+1]);
#pragma unroll
            for (int e = 0; e < 16; e++) {
                const float4* r1 = (const float4*)fc1_w + e*4;
                const float4* r2 = (const float4*)fc2_w + e*4;
                float4 a1 = __ldg(r1), b1_ = __ldg(r1+1), c1 = __ldg(r1+2), d1 = __ldg(r1+3);
                float4 a2 = __ldg(r2), b2_ = __ldg(r2+1), c2 = __ldg(r2+2), d2 = __ldg(r2+3);
                u64 p1[8] = { plo(a1), phi(a1), plo(b1_), phi(b1_), plo(c1), phi(c1), plo(d1), phi(d1) };
                u64 p2[8] = { plo(a2), phi(a2), plo(b2_), phi(b2_), plo(c2), phi(c2), plo(d2), phi(d2) };
                mu[e] = dot16s(p1, x2) + __ldg(fc1_b + e);
                lv[e] = dot16s(p2, x2) + __ldg(fc2_b + e);
            }
        }
        __syncwarp();
        if (act) {
#pragma unroll
            for (int q = 0; q < 4; q++)
                xp[n*5 + q] = make_float4(lv[4*q], lv[4*q+1], lv[4*q+2], lv[4*q+3]);
        }
        __syncwarp();
        {
            float4* o4 = (float4*)(out + R_LV + b * 208);
#pragma unroll
            for (int it = 0; it < 4; it++) {
                int idx = it * 16 + n;            // 0..63, need 0..51
                if (idx < 52) o4[idx] = xp[(idx >> 2) * 5 + (idx & 3)];
            }
        }
        __syncwarp();
        if (act) {
#pragma unroll
            for (int q = 0; q < 4; q++)
                xp[n*5 + q] = make_float4(mu[4*q], mu[4*q+1], mu[4*q+2], mu[4*q+3]);
        }
        __syncwarp();
        {
            float4* o4 = (float4*)(out + R_MU + b * 208);
#pragma unroll
            for (int it = 0; it < 4; it++) {
                int idx = it * 16 + n;
                if (idx < 52) o4[idx] = xp[(idx >> 2) * 5 + (idx & 3)];
            }
        }
    }

    // ---- decoder: recon staged into the (dead) adj slice, then coalesced out ----
    u64 mu2[8];
    if (act) {
#pragma unroll
        for (int q = 0; q < 8; q++) mu2[q] = pack2(mu[2*q], mu[2*q+1]);
    }
    float* rec = (float*)ad;            // 676 floats, 16B-aligned

#pragma unroll 1
    for (int k = 0; k < 4; k++) {
        __syncwarp();
        float t[16];
        if (act) {
#pragma unroll
            for (int d = 0; d < 16; d++) {
                float4 wa = cp.dec[k*64 + d*4],     wb = cp.dec[k*64 + d*4 + 1];
                float4 wc = cp.dec[k*64 + d*4 + 2], wd = cp.dec[k*64 + d*4 + 3];
                u64 pw[8] = { plo(wa), phi(wa), plo(wb), phi(wb),
                              plo(wc), phi(wc), plo(wd), phi(wd) };
                t[d] = dot16s(pw, mu2) + __ldg(dec_b + k*16 + d);
            }
#pragma unroll
            for (int q = 0; q < 4; q++)
                xp[n*5 + q] = make_float4(t[4*q], t[4*q+1], t[4*q+2], t[4*q+3]);
        }
        __syncwarp();
        if (act) {
            u64 t2[8];
#pragma unroll
            for (int q = 0; q < 8; q++) t2[q] = pack2(t[2*q], t[2*q+1]);
            float* rr = rec + k * 169 + n * 13;
#pragma unroll
            for (int m = 0; m < 13; m++) {
                u64 accA = 0ull, accB = 0ull;
#pragma unroll
                for (int q = 0; q < 2; q++) {
                    float4 xr = xp[m*5 + q];
                    ffma2(accA, t2[2*q],     plo(xr));
                    ffma2(accA, t2[2*q + 1], phi(xr));
                }
#pragma unroll
                for (int q = 2; q < 4; q++) {
                    float4 xr = xp[m*5 + q];
                    ffma2(accB, t2[2*q],     plo(xr));
                    ffma2(accB, t2[2*q + 1], phi(xr));
                }
                float2 fa = unpack2(accA), fb = unpack2(accB);
                float sv = (fa.x + fb.x) + (fa.y + fb.y);
                rr[m] = sv > 0.f ? sv : 0.f;
            }
        }
    }
    __syncwarp();
    // coalesced recon writeout: 676 floats = 169 float4
    {
        const float4* r4 = (const float4*)rec;
        float4* o4 = (float4*)(out + b * 676);
#pragma unroll
        for (int it = 0; it < 11; it++) {
            int idx = it * 16 + n;               // 0..175, need 0..168
            if (idx < 169) o4[idx] = r4[idx];
        }
    }
}

extern "C" void kernel_launch(void* const* d_in, const int* in_sizes, int n_in,
                              void* d_out, int out_size) {
    (void)in_sizes; (void)n_in; (void)out_size;

    // Hot weights -> constant memory (D2D, graph-capturable)
    cudaMemcpyToSymbolAsync(cp, d_in[3],  4096, offsetof(CParams, w0),  cudaMemcpyDeviceToDevice);
    cudaMemcpyToSymbolAsync(cp, d_in[5],  4096, offsetof(CParams, w1),  cudaMemcpyDeviceToDevice);
    cudaMemcpyToSymbolAsync(cp, d_in[19], 4096, offsetof(CParams, dec), cudaMemcpyDeviceToDevice);

    cudaFuncSetAttribute(vae_fused, cudaFuncAttributeMaxDynamicSharedMemorySize,
                         (int)sizeof(Smem));
    vae_fused<<<32768 / GPB, THREADS, sizeof(Smem)>>>(
        (const float*)d_in[0],  (const float*)d_in[1],  (const float*)d_in[2],
        (const float*)d_in[4],  (const float*)d_in[6],
        (const float*)d_in[7],  (const float*)d_in[8],
        (const float*)d_in[9],  (const float*)d_in[10],
        (const float*)d_in[11], (const float*)d_in[12],
        (const float*)d_in[13], (const float*)d_in[14],
        (const float*)d_in[15], (const float*)d_in[16],
        (const float*)d_in[17], (const float*)d_in[18],
        (const float*)d_in[20],
        (float*)d_out);
}